// round 6
// baseline (speedup 1.0000x reference)
#include <cuda_runtime.h>
#include <cuda_bf16.h>
#include <math.h>

#define NN   50000
#define NE   800000
#define ET   850000   // NE + NN self loops
#define IND  256
#define HID  128
#define NG   64
#define NEG_SLOPE 0.2f
#define SCAN_B ((NN + 255) / 256)   // 196

// ---------------- scratch (no allocations allowed) ----------------
__device__ float          g_bufA[NN * HID];   // fp32 attn output / gemm2 input
__device__ __nv_bfloat16  g_hb[NN * HID];     // bf16 h for gathering (12.8 MB)
__device__ float g_as[NN];
__device__ float g_ad[NN];
__device__ float g_w[ET];
__device__ int   g_batch[NN];
__device__ int   g_counts[NN];
__device__ int   g_roff[NN + 1];
__device__ int   g_cursor[NN];
__device__ int   g_csr[ET];
__device__ int   g_bsum[SCAN_B];
__device__ int   g_boff[SCAN_B];
__device__ float g_pool[NG * HID];
__device__ int   g_gcnt[NG];
__device__ int   g_flag[2];

// ---------------- dtype sniffing (int64 vs int32) ----------------
__global__ void detect_kernel(const unsigned* __restrict__ e,
                              const unsigned* __restrict__ b) {
    if (threadIdx.x == 0 && blockIdx.x == 0) {
        int nz = 0;
        for (int i = 0; i < 1024; i++) nz += (e[2 * i + 1] != 0u);
        g_flag[0] = (nz == 0);
        nz = 0;
        for (int i = 0; i < 256; i++) nz += (b[NN - 1 - 2 * i] != 0u);
        g_flag[1] = (nz == 0);
    }
}

// ---------------- zero small scratch (counts=1 encodes self loop) ----------------
__global__ void zero_kernel() {
    int stride = gridDim.x * blockDim.x;
    int i0 = blockIdx.x * blockDim.x + threadIdx.x;
    for (int j = i0; j < NN; j += stride) g_counts[j] = 1;
    for (int j = i0; j < NG * HID; j += stride) g_pool[j] = 0.f;
    for (int j = i0; j < NG; j += stride) g_gcnt[j] = 0;
}

// ---------------- histogram over dst + batch decode ----------------
__global__ void hist_kernel(const void* __restrict__ edge,
                            const void* __restrict__ batch) {
    int e64 = g_flag[0], b64 = g_flag[1];
    int i = blockIdx.x * blockDim.x + threadIdx.x;
    if (i < NE) {
        int d = e64 ? (int)((const long long*)edge)[NE + i]
                    : ((const int*)edge)[NE + i];
        atomicAdd(&g_counts[d], 1);
    }
    if (i < NN) {
        int b = b64 ? (int)((const long long*)batch)[i]
                    : ((const int*)batch)[i];
        g_batch[i] = b;
        atomicAdd(&g_gcnt[b], 1);
    }
}

// ---------------- parallel exclusive scan (3 kernels) ----------------
__global__ void scanA_kernel() {
    __shared__ int ws[8];
    int i = blockIdx.x * 256 + threadIdx.x;
    int lane = threadIdx.x & 31, wrp = threadIdx.x >> 5;
    int v = (i < NN) ? g_counts[i] : 0;
    int incl = v;
#pragma unroll
    for (int o = 1; o < 32; o <<= 1) {
        int t = __shfl_up_sync(0xffffffffu, incl, o);
        if (lane >= o) incl += t;
    }
    if (lane == 31) ws[wrp] = incl;
    __syncthreads();
    if (threadIdx.x < 8) {
        int s = ws[threadIdx.x];
        int inc2 = s;
#pragma unroll
        for (int o = 1; o < 8; o <<= 1) {
            int t = __shfl_up_sync(0xffu, inc2, o);
            if (threadIdx.x >= (unsigned)o) inc2 += t;
        }
        ws[threadIdx.x] = inc2 - s;
        if (threadIdx.x == 7) g_bsum[blockIdx.x] = inc2;
    }
    __syncthreads();
    if (i < NN) g_roff[i] = ws[wrp] + incl - v;
}

__global__ void scanB_kernel() {
    __shared__ int ws[8];
    int t = threadIdx.x;
    int lane = t & 31, wrp = t >> 5;
    int v = (t < SCAN_B) ? g_bsum[t] : 0;
    int incl = v;
#pragma unroll
    for (int o = 1; o < 32; o <<= 1) {
        int x = __shfl_up_sync(0xffffffffu, incl, o);
        if (lane >= o) incl += x;
    }
    if (lane == 31) ws[wrp] = incl;
    __syncthreads();
    if (t < 8) {
        int s = ws[t];
        int inc2 = s;
#pragma unroll
        for (int o = 1; o < 8; o <<= 1) {
            int x = __shfl_up_sync(0xffu, inc2, o);
            if (t >= o) inc2 += x;
        }
        ws[t] = inc2 - s;
    }
    __syncthreads();
    if (t < SCAN_B) g_boff[t] = ws[wrp] + incl - v;
}

__global__ void scanC_kernel() {
    int i = blockIdx.x * 256 + threadIdx.x;
    if (i == 0) g_roff[NN] = ET;
    if (i >= NN) return;
    int r = g_roff[i] + g_boff[i >> 8];
    g_roff[i] = r;
    g_cursor[i] = r;
}

// ---------------- CSR fill (decodes edge input directly) ----------------
__global__ void fill_kernel(const void* __restrict__ edge) {
    int e64 = g_flag[0];
    int i = blockIdx.x * blockDim.x + threadIdx.x;
    if (i >= ET) return;
    int s, d;
    if (i < NE) {
        if (e64) {
            s = (int)((const long long*)edge)[i];
            d = (int)((const long long*)edge)[NE + i];
        } else {
            s = ((const int*)edge)[i];
            d = ((const int*)edge)[NE + i];
        }
    } else {
        s = d = i - NE;
    }
    int p = atomicAdd(&g_cursor[d], 1);
    g_csr[p] = s;
}

// ---------------- SGEMM (bf16 output) + fused alpha epilogue ----------------
template <int K>
__global__ void __launch_bounds__(256)
gemm_kernel(const float* __restrict__ A, const float* __restrict__ B,
            __nv_bfloat16* __restrict__ C, int M,
            const float* __restrict__ asrc, const float* __restrict__ adst) {
    const int BM = 64, BN = 128, BK = 16;
    __shared__ float As[BK][BM];
    __shared__ float Bs[BK][BN];
    int tid = threadIdx.x;
    int m0 = blockIdx.x * BM;
    int ty = tid >> 5;
    int tx = tid & 31;

    float acc[8][4];
#pragma unroll
    for (int i = 0; i < 8; i++)
#pragma unroll
        for (int j = 0; j < 4; j++) acc[i][j] = 0.f;

    int arow = tid >> 2;
    int ak4  = (tid & 3) * 4;
    int bn4  = (tid & 31) * 4;
    int bk   = tid >> 5;

    for (int k0 = 0; k0 < K; k0 += BK) {
        float4 av = make_float4(0.f, 0.f, 0.f, 0.f);
        int gm = m0 + arow;
        if (gm < M) av = *(const float4*)(A + (size_t)gm * K + k0 + ak4);
        As[ak4 + 0][arow] = av.x; As[ak4 + 1][arow] = av.y;
        As[ak4 + 2][arow] = av.z; As[ak4 + 3][arow] = av.w;

        float4 bv0 = *(const float4*)(B + (size_t)(k0 + bk) * BN + bn4);
        float4 bv1 = *(const float4*)(B + (size_t)(k0 + bk + 8) * BN + bn4);
        *(float4*)&Bs[bk][bn4]     = bv0;
        *(float4*)&Bs[bk + 8][bn4] = bv1;
        __syncthreads();

#pragma unroll
        for (int k = 0; k < BK; k++) {
            float4 b4 = *(const float4*)&Bs[k][tx * 4];
            float4 a0 = *(const float4*)&As[k][ty * 8];
            float4 a1 = *(const float4*)&As[k][ty * 8 + 4];
            float a[8] = {a0.x, a0.y, a0.z, a0.w, a1.x, a1.y, a1.z, a1.w};
#pragma unroll
            for (int i = 0; i < 8; i++) {
                acc[i][0] += a[i] * b4.x;
                acc[i][1] += a[i] * b4.y;
                acc[i][2] += a[i] * b4.z;
                acc[i][3] += a[i] * b4.w;
            }
        }
        __syncthreads();
    }

    float4 asv = ((const float4*)asrc)[tx];
    float4 adv = ((const float4*)adst)[tx];
#pragma unroll
    for (int i = 0; i < 8; i++) {
        int gm = m0 + ty * 8 + i;
        float s = acc[i][0] * asv.x + acc[i][1] * asv.y +
                  acc[i][2] * asv.z + acc[i][3] * asv.w;
        float d = acc[i][0] * adv.x + acc[i][1] * adv.y +
                  acc[i][2] * adv.z + acc[i][3] * adv.w;
#pragma unroll
        for (int o = 16; o; o >>= 1) {
            s += __shfl_xor_sync(0xffffffffu, s, o);
            d += __shfl_xor_sync(0xffffffffu, d, o);
        }
        if (gm < M) {
            __nv_bfloat162 p0 = __floats2bfloat162_rn(acc[i][0], acc[i][1]);
            __nv_bfloat162 p1 = __floats2bfloat162_rn(acc[i][2], acc[i][3]);
            uint2 pk;
            pk.x = *(unsigned*)&p0;
            pk.y = *(unsigned*)&p1;
            *(uint2*)(C + (size_t)gm * BN + tx * 4) = pk;
            if (tx == 0) { g_as[gm] = s; g_ad[gm] = d; }
        }
    }
}

// ---------------- fused attention: 2 warps per dst, bf16 gathers ----------------
// block = 256 threads = 4 dst pairs. Each pair: warp0 takes first half of the
// edge list, warp1 the second half; den and acc combined through smem.
template <int POOL>
__global__ void __launch_bounds__(256)
attn_kernel(const __nv_bfloat16* __restrict__ h, const float* __restrict__ bias,
            float* __restrict__ out) {
    __shared__ float  sden[4][2];
    __shared__ float4 sacc[4][32];

    int pair = threadIdx.x >> 6;          // 0..3
    int wj   = (threadIdx.x >> 5) & 1;    // warp within pair
    int lane = threadIdx.x & 31;
    int d = blockIdx.x * 4 + pair;
    bool valid = d < NN;

    int beg = 0, end = 0;
    float add = 0.f;
    if (valid) {
        beg = g_roff[d];
        end = g_roff[d + 1];
        add = g_ad[d];
    }
    int deg  = end - beg;
    int half = (deg + 1) >> 1;
    int wbeg = beg + (wj ? half : 0);
    int wend = wj ? end : beg + half;

    // pass A: w = exp(leakyrelu(as[src]+ad[d])) for this warp's half
    float den = 0.f;
    for (int i = wbeg + lane; i < wend; i += 32) {
        float e = __ldg(&g_as[g_csr[i]]) + add;
        e = e > 0.f ? e : NEG_SLOPE * e;
        float w = __expf(e);
        g_w[i] = w;
        den += w;
    }
#pragma unroll
    for (int o = 16; o; o >>= 1) den += __shfl_xor_sync(0xffffffffu, den, o);
    if (lane == 0) sden[pair][wj] = den;
    __syncthreads();
    float inv = 1.f / (sden[pair][0] + sden[pair][1]);

    // pass B: weighted bf16 gather-aggregate over this warp's half, unroll x4
    float4 acc = make_float4(0.f, 0.f, 0.f, 0.f);
    int i = wbeg;
    for (; i + 4 <= wend; i += 4) {
        int   s0 = g_csr[i],     s1 = g_csr[i + 1];
        int   s2 = g_csr[i + 2], s3 = g_csr[i + 3];
        float c0 = g_w[i] * inv,     c1 = g_w[i + 1] * inv;
        float c2 = g_w[i + 2] * inv, c3 = g_w[i + 3] * inv;
        uint2 v0 = __ldg(&((const uint2*)(h + (size_t)s0 * HID))[lane]);
        uint2 v1 = __ldg(&((const uint2*)(h + (size_t)s1 * HID))[lane]);
        uint2 v2 = __ldg(&((const uint2*)(h + (size_t)s2 * HID))[lane]);
        uint2 v3 = __ldg(&((const uint2*)(h + (size_t)s3 * HID))[lane]);
        float2 a0 = __bfloat1622float2(*(__nv_bfloat162*)&v0.x);
        float2 b0 = __bfloat1622float2(*(__nv_bfloat162*)&v0.y);
        float2 a1 = __bfloat1622float2(*(__nv_bfloat162*)&v1.x);
        float2 b1 = __bfloat1622float2(*(__nv_bfloat162*)&v1.y);
        float2 a2 = __bfloat1622float2(*(__nv_bfloat162*)&v2.x);
        float2 b2 = __bfloat1622float2(*(__nv_bfloat162*)&v2.y);
        float2 a3 = __bfloat1622float2(*(__nv_bfloat162*)&v3.x);
        float2 b3 = __bfloat1622float2(*(__nv_bfloat162*)&v3.y);
        acc.x += c0 * a0.x + c1 * a1.x + c2 * a2.x + c3 * a3.x;
        acc.y += c0 * a0.y + c1 * a1.y + c2 * a2.y + c3 * a3.y;
        acc.z += c0 * b0.x + c1 * b1.x + c2 * b2.x + c3 * b3.x;
        acc.w += c0 * b0.y + c1 * b1.y + c2 * b2.y + c3 * b3.y;
    }
    for (; i < wend; i++) {
        int s = g_csr[i];
        float c = g_w[i] * inv;
        uint2 v = __ldg(&((const uint2*)(h + (size_t)s * HID))[lane]);
        float2 a = __bfloat1622float2(*(__nv_bfloat162*)&v.x);
        float2 b = __bfloat1622float2(*(__nv_bfloat162*)&v.y);
        acc.x += c * a.x; acc.y += c * a.y;
        acc.z += c * b.x; acc.w += c * b.y;
    }

    if (wj == 1) sacc[pair][lane] = acc;
    __syncthreads();
    if (wj == 0 && valid) {
        float4 o2 = sacc[pair][lane];
        acc.x += o2.x; acc.y += o2.y; acc.z += o2.z; acc.w += o2.w;
        float4 bb = ((const float4*)bias)[lane];
        acc.x = fmaxf(acc.x + bb.x, 0.f);
        acc.y = fmaxf(acc.y + bb.y, 0.f);
        acc.z = fmaxf(acc.z + bb.z, 0.f);
        acc.w = fmaxf(acc.w + bb.w, 0.f);
        if (POOL) {
            int g = g_batch[d];
            float* p = g_pool + g * HID + lane * 4;
            atomicAdd(p + 0, acc.x);
            atomicAdd(p + 1, acc.y);
            atomicAdd(p + 2, acc.z);
            atomicAdd(p + 3, acc.w);
        } else {
            ((float4*)(out + (size_t)d * HID))[lane] = acc;
        }
    }
}

// ---------------- classifier head ----------------
__global__ void head_kernel(const float* __restrict__ Wc,
                            const float* __restrict__ bc,
                            float* __restrict__ out) {
    int g = blockIdx.x;
    int lane = threadIdx.x;
    float s = 0.f;
#pragma unroll
    for (int j = lane; j < HID; j += 32) s += g_pool[g * HID + j] * Wc[j];
#pragma unroll
    for (int o = 16; o; o >>= 1) s += __shfl_xor_sync(0xffffffffu, s, o);
    if (lane == 0) {
        float c = fmaxf((float)g_gcnt[g], 1.f);
        float v = s / c + bc[0];
        out[g] = 1.f / (1.f + expf(-v));
    }
}

// ---------------- launch ----------------
extern "C" void kernel_launch(void* const* d_in, const int* in_sizes, int n_in,
                              void* d_out, int out_size) {
    const float* x    = (const float*)d_in[0];
    const void*  edge = d_in[1];
    const void*  batch= d_in[2];
    const float* W1   = (const float*)d_in[3];
    const float* as1  = (const float*)d_in[4];
    const float* ad1  = (const float*)d_in[5];
    const float* b1   = (const float*)d_in[6];
    const float* W2   = (const float*)d_in[7];
    const float* as2  = (const float*)d_in[8];
    const float* ad2  = (const float*)d_in[9];
    const float* b2   = (const float*)d_in[10];
    const float* Wc   = (const float*)d_in[11];
    const float* bc   = (const float*)d_in[12];
    float* out = (float*)d_out;
    (void)in_sizes; (void)n_in; (void)out_size;

    float* bufA; cudaGetSymbolAddress((void**)&bufA, g_bufA);
    __nv_bfloat16* hb; cudaGetSymbolAddress((void**)&hb, g_hb);

    const int EB = (ET + 255) / 256;
    const int HB = (NE + 255) / 256;
    const int AB = (NN + 3) / 4;         // attn: 4 dsts per 256-thread block

    detect_kernel<<<1, 32>>>((const unsigned*)edge, (const unsigned*)batch);
    zero_kernel<<<64, 256>>>();
    hist_kernel<<<HB, 256>>>(edge, batch);
    scanA_kernel<<<SCAN_B, 256>>>();
    scanB_kernel<<<1, 256>>>();
    scanC_kernel<<<SCAN_B, 256>>>();
    fill_kernel<<<EB, 256>>>(edge);

    // ---- layer 1 ----
    gemm_kernel<IND><<<(NN + 63) / 64, 256>>>(x, W1, hb, NN, as1, ad1);
    attn_kernel<0><<<AB, 256>>>(hb, b1, bufA);

    // ---- layer 2 ----
    gemm_kernel<HID><<<(NN + 63) / 64, 256>>>(bufA, W2, hb, NN, as2, ad2);
    attn_kernel<1><<<AB, 256>>>(hb, b2, nullptr);

    head_kernel<<<NG, 32>>>(Wc, bc, out);
}

// round 7
// speedup vs baseline: 1.1855x; 1.1855x over previous
#include <cuda_runtime.h>
#include <cuda_bf16.h>
#include <math.h>

#define NN   50000
#define NE   800000
#define ET   850000   // NE + NN self loops
#define IND  256
#define HID  128
#define NG   64
#define NEG_SLOPE 0.2f
#define SCAN_B ((NN + 255) / 256)   // 196

// ---------------- scratch (no allocations allowed) ----------------
__device__ float          g_bufA[NN * HID];   // fp32 attn output / gemm2 input
__device__ __nv_bfloat16  g_hb[NN * HID];     // bf16 h for gathering (12.8 MB)
__device__ float g_as[NN];
__device__ float g_ad[NN];
__device__ float g_w[ET];
__device__ int   g_batch[NN];
__device__ int   g_counts[NN];
__device__ int   g_roff[NN + 1];
__device__ int   g_cursor[NN];
__device__ int   g_csr[ET];
__device__ int   g_bsum[SCAN_B];
__device__ int   g_boff[SCAN_B];
__device__ float g_pool[NG * HID];
__device__ int   g_gcnt[NG];
__device__ int   g_flag[2];

// ---------------- dtype sniffing (int64 vs int32) ----------------
__global__ void detect_kernel(const unsigned* __restrict__ e,
                              const unsigned* __restrict__ b) {
    if (threadIdx.x == 0 && blockIdx.x == 0) {
        int nz = 0;
        for (int i = 0; i < 1024; i++) nz += (e[2 * i + 1] != 0u);
        g_flag[0] = (nz == 0);
        nz = 0;
        for (int i = 0; i < 256; i++) nz += (b[NN - 1 - 2 * i] != 0u);
        g_flag[1] = (nz == 0);
    }
}

// ---------------- zero small scratch (counts=1 encodes self loop) ----------------
__global__ void zero_kernel() {
    int stride = gridDim.x * blockDim.x;
    int i0 = blockIdx.x * blockDim.x + threadIdx.x;
    for (int j = i0; j < NN; j += stride) g_counts[j] = 1;
    for (int j = i0; j < NG * HID; j += stride) g_pool[j] = 0.f;
    for (int j = i0; j < NG; j += stride) g_gcnt[j] = 0;
}

// ---------------- histogram over dst + batch decode ----------------
__global__ void hist_kernel(const void* __restrict__ edge,
                            const void* __restrict__ batch) {
    int e64 = g_flag[0], b64 = g_flag[1];
    int i = blockIdx.x * blockDim.x + threadIdx.x;
    if (i < NE) {
        int d = e64 ? (int)((const long long*)edge)[NE + i]
                    : ((const int*)edge)[NE + i];
        atomicAdd(&g_counts[d], 1);
    }
    if (i < NN) {
        int b = b64 ? (int)((const long long*)batch)[i]
                    : ((const int*)batch)[i];
        g_batch[i] = b;
        atomicAdd(&g_gcnt[b], 1);
    }
}

// ---------------- parallel exclusive scan (3 kernels) ----------------
__global__ void scanA_kernel() {
    __shared__ int ws[8];
    int i = blockIdx.x * 256 + threadIdx.x;
    int lane = threadIdx.x & 31, wrp = threadIdx.x >> 5;
    int v = (i < NN) ? g_counts[i] : 0;
    int incl = v;
#pragma unroll
    for (int o = 1; o < 32; o <<= 1) {
        int t = __shfl_up_sync(0xffffffffu, incl, o);
        if (lane >= o) incl += t;
    }
    if (lane == 31) ws[wrp] = incl;
    __syncthreads();
    if (threadIdx.x < 8) {
        int s = ws[threadIdx.x];
        int inc2 = s;
#pragma unroll
        for (int o = 1; o < 8; o <<= 1) {
            int t = __shfl_up_sync(0xffu, inc2, o);
            if (threadIdx.x >= (unsigned)o) inc2 += t;
        }
        ws[threadIdx.x] = inc2 - s;
        if (threadIdx.x == 7) g_bsum[blockIdx.x] = inc2;
    }
    __syncthreads();
    if (i < NN) g_roff[i] = ws[wrp] + incl - v;
}

__global__ void scanB_kernel() {
    __shared__ int ws[8];
    int t = threadIdx.x;
    int lane = t & 31, wrp = t >> 5;
    int v = (t < SCAN_B) ? g_bsum[t] : 0;
    int incl = v;
#pragma unroll
    for (int o = 1; o < 32; o <<= 1) {
        int x = __shfl_up_sync(0xffffffffu, incl, o);
        if (lane >= o) incl += x;
    }
    if (lane == 31) ws[wrp] = incl;
    __syncthreads();
    if (t < 8) {
        int s = ws[t];
        int inc2 = s;
#pragma unroll
        for (int o = 1; o < 8; o <<= 1) {
            int x = __shfl_up_sync(0xffu, inc2, o);
            if (t >= o) inc2 += x;
        }
        ws[t] = inc2 - s;
    }
    __syncthreads();
    if (t < SCAN_B) g_boff[t] = ws[wrp] + incl - v;
}

__global__ void scanC_kernel() {
    int i = blockIdx.x * 256 + threadIdx.x;
    if (i == 0) g_roff[NN] = ET;
    if (i >= NN) return;
    int r = g_roff[i] + g_boff[i >> 8];
    g_roff[i] = r;
    g_cursor[i] = r;
}

// ---------------- CSR fill (decodes edge input directly) ----------------
__global__ void fill_kernel(const void* __restrict__ edge) {
    int e64 = g_flag[0];
    int i = blockIdx.x * blockDim.x + threadIdx.x;
    if (i >= ET) return;
    int s, d;
    if (i < NE) {
        if (e64) {
            s = (int)((const long long*)edge)[i];
            d = (int)((const long long*)edge)[NE + i];
        } else {
            s = ((const int*)edge)[i];
            d = ((const int*)edge)[NE + i];
        }
    } else {
        s = d = i - NE;
    }
    int p = atomicAdd(&g_cursor[d], 1);
    g_csr[p] = s;
}

// ---------------- SGEMM (bf16 output) + fused alpha epilogue ----------------
template <int K>
__global__ void __launch_bounds__(256)
gemm_kernel(const float* __restrict__ A, const float* __restrict__ B,
            __nv_bfloat16* __restrict__ C, int M,
            const float* __restrict__ asrc, const float* __restrict__ adst) {
    const int BM = 64, BN = 128, BK = 16;
    __shared__ float As[BK][BM];
    __shared__ float Bs[BK][BN];
    int tid = threadIdx.x;
    int m0 = blockIdx.x * BM;
    int ty = tid >> 5;
    int tx = tid & 31;

    float acc[8][4];
#pragma unroll
    for (int i = 0; i < 8; i++)
#pragma unroll
        for (int j = 0; j < 4; j++) acc[i][j] = 0.f;

    int arow = tid >> 2;
    int ak4  = (tid & 3) * 4;
    int bn4  = (tid & 31) * 4;
    int bk   = tid >> 5;

    for (int k0 = 0; k0 < K; k0 += BK) {
        float4 av = make_float4(0.f, 0.f, 0.f, 0.f);
        int gm = m0 + arow;
        if (gm < M) av = *(const float4*)(A + (size_t)gm * K + k0 + ak4);
        As[ak4 + 0][arow] = av.x; As[ak4 + 1][arow] = av.y;
        As[ak4 + 2][arow] = av.z; As[ak4 + 3][arow] = av.w;

        float4 bv0 = *(const float4*)(B + (size_t)(k0 + bk) * BN + bn4);
        float4 bv1 = *(const float4*)(B + (size_t)(k0 + bk + 8) * BN + bn4);
        *(float4*)&Bs[bk][bn4]     = bv0;
        *(float4*)&Bs[bk + 8][bn4] = bv1;
        __syncthreads();

#pragma unroll
        for (int k = 0; k < BK; k++) {
            float4 b4 = *(const float4*)&Bs[k][tx * 4];
            float4 a0 = *(const float4*)&As[k][ty * 8];
            float4 a1 = *(const float4*)&As[k][ty * 8 + 4];
            float a[8] = {a0.x, a0.y, a0.z, a0.w, a1.x, a1.y, a1.z, a1.w};
#pragma unroll
            for (int i = 0; i < 8; i++) {
                acc[i][0] += a[i] * b4.x;
                acc[i][1] += a[i] * b4.y;
                acc[i][2] += a[i] * b4.z;
                acc[i][3] += a[i] * b4.w;
            }
        }
        __syncthreads();
    }

    float4 asv = ((const float4*)asrc)[tx];
    float4 adv = ((const float4*)adst)[tx];
#pragma unroll
    for (int i = 0; i < 8; i++) {
        int gm = m0 + ty * 8 + i;
        float s = acc[i][0] * asv.x + acc[i][1] * asv.y +
                  acc[i][2] * asv.z + acc[i][3] * asv.w;
        float d = acc[i][0] * adv.x + acc[i][1] * adv.y +
                  acc[i][2] * adv.z + acc[i][3] * adv.w;
#pragma unroll
        for (int o = 16; o; o >>= 1) {
            s += __shfl_xor_sync(0xffffffffu, s, o);
            d += __shfl_xor_sync(0xffffffffu, d, o);
        }
        if (gm < M) {
            __nv_bfloat162 p0 = __floats2bfloat162_rn(acc[i][0], acc[i][1]);
            __nv_bfloat162 p1 = __floats2bfloat162_rn(acc[i][2], acc[i][3]);
            uint2 pk;
            pk.x = *(unsigned*)&p0;
            pk.y = *(unsigned*)&p1;
            *(uint2*)(C + (size_t)gm * BN + tx * 4) = pk;
            if (tx == 0) { g_as[gm] = s; g_ad[gm] = d; }
        }
    }
}

// ---------------- fused attention: warp per dst (R5 structure), bf16 gathers ----------------
template <int POOL>
__global__ void __launch_bounds__(256)
attn_kernel(const __nv_bfloat16* __restrict__ h, const float* __restrict__ bias,
            float* __restrict__ out) {
    int d = blockIdx.x * 8 + (threadIdx.x >> 5);
    if (d >= NN) return;
    int lane = threadIdx.x & 31;
    int beg = g_roff[d], end = g_roff[d + 1];
    float add = g_ad[d];

    // pass A: w = exp(leakyrelu(e)), cache in g_w, accumulate denominator
    float den = 0.f;
    for (int i = beg + lane; i < end; i += 32) {
        float e = __ldg(&g_as[g_csr[i]]) + add;
        e = e > 0.f ? e : NEG_SLOPE * e;
        float w = __expf(e);
        g_w[i] = w;
        den += w;
    }
#pragma unroll
    for (int o = 16; o; o >>= 1) den += __shfl_xor_sync(0xffffffffu, den, o);
    float inv = 1.f / den;
    __syncwarp();

    // pass B: weighted bf16 gather-aggregate, unroll x4
    float4 acc = make_float4(0.f, 0.f, 0.f, 0.f);
    int i = beg;
    for (; i + 4 <= end; i += 4) {
        int   s0 = g_csr[i],     s1 = g_csr[i + 1];
        int   s2 = g_csr[i + 2], s3 = g_csr[i + 3];
        float c0 = g_w[i] * inv,     c1 = g_w[i + 1] * inv;
        float c2 = g_w[i + 2] * inv, c3 = g_w[i + 3] * inv;
        uint2 v0 = __ldg(&((const uint2*)(h + (size_t)s0 * HID))[lane]);
        uint2 v1 = __ldg(&((const uint2*)(h + (size_t)s1 * HID))[lane]);
        uint2 v2 = __ldg(&((const uint2*)(h + (size_t)s2 * HID))[lane]);
        uint2 v3 = __ldg(&((const uint2*)(h + (size_t)s3 * HID))[lane]);
        float2 a0 = __bfloat1622float2(*(__nv_bfloat162*)&v0.x);
        float2 b0 = __bfloat1622float2(*(__nv_bfloat162*)&v0.y);
        float2 a1 = __bfloat1622float2(*(__nv_bfloat162*)&v1.x);
        float2 b1 = __bfloat1622float2(*(__nv_bfloat162*)&v1.y);
        float2 a2 = __bfloat1622float2(*(__nv_bfloat162*)&v2.x);
        float2 b2 = __bfloat1622float2(*(__nv_bfloat162*)&v2.y);
        float2 a3 = __bfloat1622float2(*(__nv_bfloat162*)&v3.x);
        float2 b3 = __bfloat1622float2(*(__nv_bfloat162*)&v3.y);
        acc.x += c0 * a0.x + c1 * a1.x + c2 * a2.x + c3 * a3.x;
        acc.y += c0 * a0.y + c1 * a1.y + c2 * a2.y + c3 * a3.y;
        acc.z += c0 * b0.x + c1 * b1.x + c2 * b2.x + c3 * b3.x;
        acc.w += c0 * b0.y + c1 * b1.y + c2 * b2.y + c3 * b3.y;
    }
    for (; i < end; i++) {
        int s = g_csr[i];
        float c = g_w[i] * inv;
        uint2 v = __ldg(&((const uint2*)(h + (size_t)s * HID))[lane]);
        float2 a = __bfloat1622float2(*(__nv_bfloat162*)&v.x);
        float2 b = __bfloat1622float2(*(__nv_bfloat162*)&v.y);
        acc.x += c * a.x; acc.y += c * a.y;
        acc.z += c * b.x; acc.w += c * b.y;
    }

    float4 bb = ((const float4*)bias)[lane];
    acc.x = fmaxf(acc.x + bb.x, 0.f);
    acc.y = fmaxf(acc.y + bb.y, 0.f);
    acc.z = fmaxf(acc.z + bb.z, 0.f);
    acc.w = fmaxf(acc.w + bb.w, 0.f);

    if (POOL) {
        int g = g_batch[d];
        float* p = g_pool + g * HID + lane * 4;
        atomicAdd(p + 0, acc.x);
        atomicAdd(p + 1, acc.y);
        atomicAdd(p + 2, acc.z);
        atomicAdd(p + 3, acc.w);
    } else {
        ((float4*)(out + (size_t)d * HID))[lane] = acc;
    }
}

// ---------------- classifier head ----------------
__global__ void head_kernel(const float* __restrict__ Wc,
                            const float* __restrict__ bc,
                            float* __restrict__ out) {
    int g = blockIdx.x;
    int lane = threadIdx.x;
    float s = 0.f;
#pragma unroll
    for (int j = lane; j < HID; j += 32) s += g_pool[g * HID + j] * Wc[j];
#pragma unroll
    for (int o = 16; o; o >>= 1) s += __shfl_xor_sync(0xffffffffu, s, o);
    if (lane == 0) {
        float c = fmaxf((float)g_gcnt[g], 1.f);
        float v = s / c + bc[0];
        out[g] = 1.f / (1.f + expf(-v));
    }
}

// ---------------- launch ----------------
extern "C" void kernel_launch(void* const* d_in, const int* in_sizes, int n_in,
                              void* d_out, int out_size) {
    const float* x    = (const float*)d_in[0];
    const void*  edge = d_in[1];
    const void*  batch= d_in[2];
    const float* W1   = (const float*)d_in[3];
    const float* as1  = (const float*)d_in[4];
    const float* ad1  = (const float*)d_in[5];
    const float* b1   = (const float*)d_in[6];
    const float* W2   = (const float*)d_in[7];
    const float* as2  = (const float*)d_in[8];
    const float* ad2  = (const float*)d_in[9];
    const float* b2   = (const float*)d_in[10];
    const float* Wc   = (const float*)d_in[11];
    const float* bc   = (const float*)d_in[12];
    float* out = (float*)d_out;
    (void)in_sizes; (void)n_in; (void)out_size;

    float* bufA; cudaGetSymbolAddress((void**)&bufA, g_bufA);
    __nv_bfloat16* hb; cudaGetSymbolAddress((void**)&hb, g_hb);

    const int EB = (ET + 255) / 256;
    const int HB = (NE + 255) / 256;
    const int WB = (NN + 7) / 8;

    detect_kernel<<<1, 32>>>((const unsigned*)edge, (const unsigned*)batch);
    zero_kernel<<<64, 256>>>();
    hist_kernel<<<HB, 256>>>(edge, batch);
    scanA_kernel<<<SCAN_B, 256>>>();
    scanB_kernel<<<1, 256>>>();
    scanC_kernel<<<SCAN_B, 256>>>();
    fill_kernel<<<EB, 256>>>(edge);

    // ---- layer 1 ----
    gemm_kernel<IND><<<(NN + 63) / 64, 256>>>(x, W1, hb, NN, as1, ad1);
    attn_kernel<0><<<WB, 256>>>(hb, b1, bufA);

    // ---- layer 2 ----
    gemm_kernel<HID><<<(NN + 63) / 64, 256>>>(bufA, W2, hb, NN, as2, ad2);
    attn_kernel<1><<<WB, 256>>>(hb, b2, nullptr);

    head_kernel<<<NG, 32>>>(Wc, bc, out);
}

// round 10
// speedup vs baseline: 1.4966x; 1.2624x over previous
#include <cuda_runtime.h>
#include <cuda_bf16.h>
#include <cstdint>
#include <math.h>

#define NN   50000
#define NE   800000
#define ET   850000   // NE + NN self loops
#define IND  256
#define HID  128
#define NG   64
#define NEG_SLOPE 0.2f
#define SCAN_B ((NN + 255) / 256)   // 196

// ---------------- scratch (no allocations allowed) ----------------
__device__ float          g_bufA[NN * HID];   // fp32 attn output / gemm2 input
__device__ __nv_bfloat16  g_hb[NN * HID];     // bf16 h for gathering (12.8 MB)
__device__ float g_as[NN];
__device__ float g_ad[NN];
__device__ float g_w[ET];
__device__ int   g_batch[NN];
__device__ int   g_counts[NN];
__device__ int   g_roff[NN + 1];
__device__ int   g_cursor[NN];
__device__ int   g_csr[ET];
__device__ int   g_bsum[SCAN_B];
__device__ int   g_boff[SCAN_B];
__device__ float g_pool[NG * HID];
__device__ int   g_gcnt[NG];
__device__ int   g_flag[2];

// ---------------- dtype sniffing (parallel) ----------------
__global__ void detect_kernel(const unsigned* __restrict__ e,
                              const unsigned* __restrict__ b) {
    __shared__ int r[2];
    int t = threadIdx.x;
    if (t < 2) r[t] = 0;
    __syncthreads();
    int a = 0;
    for (int i = t; i < 1024; i += 256) a |= (e[2 * i + 1] != 0u);
    int bb = (t < 256) ? (b[NN - 1 - 2 * t] != 0u) : 0;
    if (a) atomicOr(&r[0], 1);
    if (bb) atomicOr(&r[1], 1);
    __syncthreads();
    if (t == 0) { g_flag[0] = !r[0]; g_flag[1] = !r[1]; }
}

// ---------------- zero small scratch (counts=1 encodes self loop) ----------------
__global__ void zero_kernel() {
    int stride = gridDim.x * blockDim.x;
    int i0 = blockIdx.x * blockDim.x + threadIdx.x;
    for (int j = i0; j < NN; j += stride) g_counts[j] = 1;
    for (int j = i0; j < NG * HID; j += stride) g_pool[j] = 0.f;
    for (int j = i0; j < NG; j += stride) g_gcnt[j] = 0;
}

// ---------------- histogram over dst + batch decode ----------------
__global__ void hist_kernel(const void* __restrict__ edge,
                            const void* __restrict__ batch) {
    int e64 = g_flag[0], b64 = g_flag[1];
    int i = blockIdx.x * blockDim.x + threadIdx.x;
    if (i < NE) {
        int d = e64 ? (int)((const long long*)edge)[NE + i]
                    : ((const int*)edge)[NE + i];
        atomicAdd(&g_counts[d], 1);
    }
    if (i < NN) {
        int b = b64 ? (int)((const long long*)batch)[i]
                    : ((const int*)batch)[i];
        g_batch[i] = b;
        atomicAdd(&g_gcnt[b], 1);
    }
}

// ---------------- parallel exclusive scan (3 kernels) ----------------
__global__ void scanA_kernel() {
    __shared__ int ws[8];
    int i = blockIdx.x * 256 + threadIdx.x;
    int lane = threadIdx.x & 31, wrp = threadIdx.x >> 5;
    int v = (i < NN) ? g_counts[i] : 0;
    int incl = v;
#pragma unroll
    for (int o = 1; o < 32; o <<= 1) {
        int t = __shfl_up_sync(0xffffffffu, incl, o);
        if (lane >= o) incl += t;
    }
    if (lane == 31) ws[wrp] = incl;
    __syncthreads();
    if (threadIdx.x < 8) {
        int s = ws[threadIdx.x];
        int inc2 = s;
#pragma unroll
        for (int o = 1; o < 8; o <<= 1) {
            int t = __shfl_up_sync(0xffu, inc2, o);
            if (threadIdx.x >= (unsigned)o) inc2 += t;
        }
        ws[threadIdx.x] = inc2 - s;
        if (threadIdx.x == 7) g_bsum[blockIdx.x] = inc2;
    }
    __syncthreads();
    if (i < NN) g_roff[i] = ws[wrp] + incl - v;
}

__global__ void scanB_kernel() {
    __shared__ int ws[8];
    int t = threadIdx.x;
    int lane = t & 31, wrp = t >> 5;
    int v = (t < SCAN_B) ? g_bsum[t] : 0;
    int incl = v;
#pragma unroll
    for (int o = 1; o < 32; o <<= 1) {
        int x = __shfl_up_sync(0xffffffffu, incl, o);
        if (lane >= o) incl += x;
    }
    if (lane == 31) ws[wrp] = incl;
    __syncthreads();
    if (t < 8) {
        int s = ws[t];
        int inc2 = s;
#pragma unroll
        for (int o = 1; o < 8; o <<= 1) {
            int x = __shfl_up_sync(0xffu, inc2, o);
            if (t >= o) inc2 += x;
        }
        ws[t] = inc2 - s;
    }
    __syncthreads();
    if (t < SCAN_B) g_boff[t] = ws[wrp] + incl - v;
}

__global__ void scanC_kernel() {
    int i = blockIdx.x * 256 + threadIdx.x;
    if (i == 0) g_roff[NN] = ET;
    if (i >= NN) return;
    int r = g_roff[i] + g_boff[i >> 8];
    g_roff[i] = r;
    g_cursor[i] = r;
}

// ---------------- CSR fill (decodes edge input directly) ----------------
__global__ void fill_kernel(const void* __restrict__ edge) {
    int e64 = g_flag[0];
    int i = blockIdx.x * blockDim.x + threadIdx.x;
    if (i >= ET) return;
    int s, d;
    if (i < NE) {
        if (e64) {
            s = (int)((const long long*)edge)[i];
            d = (int)((const long long*)edge)[NE + i];
        } else {
            s = ((const int*)edge)[i];
            d = ((const int*)edge)[NE + i];
        }
    } else {
        s = d = i - NE;
    }
    int p = atomicAdd(&g_cursor[d], 1);
    g_csr[p] = s;
}

// ================= bf16 mma.sync GEMM =================
// C[M,128](bf16) = A[M,K](fp32->bf16) @ W[K,128](fp32->bf16), fp32 accum.
// Block: 128x128 tile, 256 threads = 4(M) x 2(N) warps, warp = 32x64.
// mma.sync.aligned.m16n8k16.row.col.f32.bf16.bf16.f32

__device__ __forceinline__ uint32_t smem_u32(const void* p) {
    uint32_t a;
    asm("{ .reg .u64 t; cvta.to.shared.u64 t, %1; cvt.u32.u64 %0, t; }"
        : "=r"(a) : "l"(p));
    return a;
}

#define LDM_X4(r0, r1, r2, r3, addr) \
    asm volatile("ldmatrix.sync.aligned.m8n8.x4.shared.b16 {%0,%1,%2,%3}, [%4];" \
        : "=r"(r0), "=r"(r1), "=r"(r2), "=r"(r3) : "r"(addr))
#define LDM_X4T(r0, r1, r2, r3, addr) \
    asm volatile("ldmatrix.sync.aligned.m8n8.x4.trans.shared.b16 {%0,%1,%2,%3}, [%4];" \
        : "=r"(r0), "=r"(r1), "=r"(r2), "=r"(r3) : "r"(addr))
#define MMA16816(c, a0, a1, a2, a3, b0, b1) \
    asm volatile("mma.sync.aligned.m16n8k16.row.col.f32.bf16.bf16.f32 " \
        "{%0,%1,%2,%3}, {%4,%5,%6,%7}, {%8,%9}, {%0,%1,%2,%3};" \
        : "+f"((c)[0]), "+f"((c)[1]), "+f"((c)[2]), "+f"((c)[3]) \
        : "r"(a0), "r"(a1), "r"(a2), "r"(a3), "r"(b0), "r"(b1))

template <int K>
__global__ void __launch_bounds__(256)
mma_gemm_kernel(const float* __restrict__ A, const float* __restrict__ W,
                __nv_bfloat16* __restrict__ C, int M) {
    constexpr int LDA = K + 8;        // bf16 elems; (LDA*2)%128 = 16 -> conflict-free
    constexpr int LDW = HID + 8;      // 136
    extern __shared__ char smem[];
    __nv_bfloat16* sA = (__nv_bfloat16*)smem;                   // 128 x LDA
    __nv_bfloat16* sW = (__nv_bfloat16*)(smem + 128 * LDA * 2); // K x LDW

    int tid = threadIdx.x;
    int wid = tid >> 5, lane = tid & 31;
    int m0 = blockIdx.x * 128;

    // ---- stage A (fp32 -> bf16)
    for (int idx = tid; idx < 128 * K / 8; idx += 256) {
        int row = idx / (K / 8);
        int kv  = (idx % (K / 8)) * 8;
        int gm  = m0 + row;
        float4 f0 = make_float4(0.f, 0.f, 0.f, 0.f), f1 = f0;
        if (gm < M) {
            f0 = *(const float4*)(A + (size_t)gm * K + kv);
            f1 = *(const float4*)(A + (size_t)gm * K + kv + 4);
        }
        __nv_bfloat162 p0 = __floats2bfloat162_rn(f0.x, f0.y);
        __nv_bfloat162 p1 = __floats2bfloat162_rn(f0.z, f0.w);
        __nv_bfloat162 p2 = __floats2bfloat162_rn(f1.x, f1.y);
        __nv_bfloat162 p3 = __floats2bfloat162_rn(f1.z, f1.w);
        uint4 pk;
        pk.x = *(unsigned*)&p0; pk.y = *(unsigned*)&p1;
        pk.z = *(unsigned*)&p2; pk.w = *(unsigned*)&p3;
        *(uint4*)(sA + row * LDA + kv) = pk;
    }
    // ---- stage W (fp32 -> bf16); W is [K][128] row-major already
    for (int idx = tid; idx < K * HID / 8; idx += 256) {
        int k = idx / (HID / 8);
        int n = (idx % (HID / 8)) * 8;
        float4 f0 = *(const float4*)(W + (size_t)k * HID + n);
        float4 f1 = *(const float4*)(W + (size_t)k * HID + n + 4);
        __nv_bfloat162 p0 = __floats2bfloat162_rn(f0.x, f0.y);
        __nv_bfloat162 p1 = __floats2bfloat162_rn(f0.z, f0.w);
        __nv_bfloat162 p2 = __floats2bfloat162_rn(f1.x, f1.y);
        __nv_bfloat162 p3 = __floats2bfloat162_rn(f1.z, f1.w);
        uint4 pk;
        pk.x = *(unsigned*)&p0; pk.y = *(unsigned*)&p1;
        pk.z = *(unsigned*)&p2; pk.w = *(unsigned*)&p3;
        *(uint4*)(sW + k * LDW + n) = pk;
    }
    __syncthreads();

    const int wm = (wid & 3) * 32;    // warp M offset in tile
    const int wn = (wid >> 2) * 64;   // warp N offset

    float acc[2][8][4];
#pragma unroll
    for (int mt = 0; mt < 2; mt++)
#pragma unroll
        for (int nt = 0; nt < 8; nt++)
#pragma unroll
            for (int j = 0; j < 4; j++) acc[mt][nt][j] = 0.f;

    uint32_t sAu = smem_u32(sA);
    uint32_t sWu = smem_u32(sW);

#pragma unroll
    for (int ks = 0; ks < K / 16; ks++) {
        int k = ks * 16;
        uint32_t a[2][4];
#pragma unroll
        for (int mt = 0; mt < 2; mt++) {
            uint32_t addr = sAu +
                ((wm + mt * 16 + (lane & 15)) * LDA + k + (lane >> 4) * 8) * 2;
            LDM_X4(a[mt][0], a[mt][1], a[mt][2], a[mt][3], addr);
        }
        uint32_t b[8][2];
#pragma unroll
        for (int np = 0; np < 4; np++) {
            uint32_t addr = sWu +
                ((k + (lane & 15)) * LDW + wn + np * 16 + (lane >> 4) * 8) * 2;
            uint32_t r0, r1, r2, r3;
            LDM_X4T(r0, r1, r2, r3, addr);
            b[np * 2][0] = r0;     b[np * 2][1] = r1;
            b[np * 2 + 1][0] = r2; b[np * 2 + 1][1] = r3;
        }
#pragma unroll
        for (int mt = 0; mt < 2; mt++)
#pragma unroll
            for (int nt = 0; nt < 8; nt++)
                MMA16816(acc[mt][nt], a[mt][0], a[mt][1], a[mt][2], a[mt][3],
                         b[nt][0], b[nt][1]);
    }

    // ---- epilogue: bf16 stores
    int g = lane >> 2, tg = lane & 3;
#pragma unroll
    for (int mt = 0; mt < 2; mt++) {
        int r0 = m0 + wm + mt * 16 + g;
        int r1 = r0 + 8;
#pragma unroll
        for (int nt = 0; nt < 8; nt++) {
            int c = wn + nt * 8 + tg * 2;
            if (r0 < M) {
                __nv_bfloat162 p = __floats2bfloat162_rn(acc[mt][nt][0], acc[mt][nt][1]);
                *(unsigned*)(C + (size_t)r0 * HID + c) = *(unsigned*)&p;
            }
            if (r1 < M) {
                __nv_bfloat162 p = __floats2bfloat162_rn(acc[mt][nt][2], acc[mt][nt][3]);
                *(unsigned*)(C + (size_t)r1 * HID + c) = *(unsigned*)&p;
            }
        }
    }
}

// ---------------- alpha dots from bf16 h ----------------
__global__ void alpha_kernel(const __nv_bfloat16* __restrict__ h,
                             const float* __restrict__ asrc,
                             const float* __restrict__ adst) {
    int node = blockIdx.x * 8 + (threadIdx.x >> 5);
    if (node >= NN) return;
    int lane = threadIdx.x & 31;
    uint2 v = __ldg(&((const uint2*)(h + (size_t)node * HID))[lane]);
    float2 a = __bfloat1622float2(*(__nv_bfloat162*)&v.x);
    float2 b = __bfloat1622float2(*(__nv_bfloat162*)&v.y);
    float4 sv = __ldg(&((const float4*)asrc)[lane]);
    float4 dv = __ldg(&((const float4*)adst)[lane]);
    float s = a.x * sv.x + a.y * sv.y + b.x * sv.z + b.y * sv.w;
    float d = a.x * dv.x + a.y * dv.y + b.x * dv.z + b.y * dv.w;
#pragma unroll
    for (int o = 16; o; o >>= 1) {
        s += __shfl_xor_sync(0xffffffffu, s, o);
        d += __shfl_xor_sync(0xffffffffu, d, o);
    }
    if (lane == 0) { g_as[node] = s; g_ad[node] = d; }
}

// ---------------- fused attention: warp per dst, bf16 gathers ----------------
template <int POOL>
__global__ void __launch_bounds__(256)
attn_kernel(const __nv_bfloat16* __restrict__ h, const float* __restrict__ bias,
            float* __restrict__ out) {
    int d = blockIdx.x * 8 + (threadIdx.x >> 5);
    if (d >= NN) return;
    int lane = threadIdx.x & 31;
    int beg = g_roff[d], end = g_roff[d + 1];
    float add = g_ad[d];

    float den = 0.f;
    for (int i = beg + lane; i < end; i += 32) {
        float e = __ldg(&g_as[g_csr[i]]) + add;
        e = e > 0.f ? e : NEG_SLOPE * e;
        float w = __expf(e);
        g_w[i] = w;
        den += w;
    }
#pragma unroll
    for (int o = 16; o; o >>= 1) den += __shfl_xor_sync(0xffffffffu, den, o);
    float inv = 1.f / den;
    __syncwarp();

    float4 acc = make_float4(0.f, 0.f, 0.f, 0.f);
    int i = beg;
    for (; i + 4 <= end; i += 4) {
        int   s0 = g_csr[i],     s1 = g_csr[i + 1];
        int   s2 = g_csr[i + 2], s3 = g_csr[i + 3];
        float c0 = g_w[i] * inv,     c1 = g_w[i + 1] * inv;
        float c2 = g_w[i + 2] * inv, c3 = g_w[i + 3] * inv;
        uint2 v0 = __ldg(&((const uint2*)(h + (size_t)s0 * HID))[lane]);
        uint2 v1 = __ldg(&((const uint2*)(h + (size_t)s1 * HID))[lane]);
        uint2 v2 = __ldg(&((const uint2*)(h + (size_t)s2 * HID))[lane]);
        uint2 v3 = __ldg(&((const uint2*)(h + (size_t)s3 * HID))[lane]);
        float2 a0 = __bfloat1622float2(*(__nv_bfloat162*)&v0.x);
        float2 b0 = __bfloat1622float2(*(__nv_bfloat162*)&v0.y);
        float2 a1 = __bfloat1622float2(*(__nv_bfloat162*)&v1.x);
        float2 b1 = __bfloat1622float2(*(__nv_bfloat162*)&v1.y);
        float2 a2 = __bfloat1622float2(*(__nv_bfloat162*)&v2.x);
        float2 b2 = __bfloat1622float2(*(__nv_bfloat162*)&v2.y);
        float2 a3 = __bfloat1622float2(*(__nv_bfloat162*)&v3.x);
        float2 b3 = __bfloat1622float2(*(__nv_bfloat162*)&v3.y);
        acc.x += c0 * a0.x + c1 * a1.x + c2 * a2.x + c3 * a3.x;
        acc.y += c0 * a0.y + c1 * a1.y + c2 * a2.y + c3 * a3.y;
        acc.z += c0 * b0.x + c1 * b1.x + c2 * b2.x + c3 * b3.x;
        acc.w += c0 * b0.y + c1 * b1.y + c2 * b2.y + c3 * b3.y;
    }
    for (; i < end; i++) {
        int s = g_csr[i];
        float c = g_w[i] * inv;
        uint2 v = __ldg(&((const uint2*)(h + (size_t)s * HID))[lane]);
        float2 a = __bfloat1622float2(*(__nv_bfloat162*)&v.x);
        float2 b = __bfloat1622float2(*(__nv_bfloat162*)&v.y);
        acc.x += c * a.x; acc.y += c * a.y;
        acc.z += c * b.x; acc.w += c * b.y;
    }

    float4 bb = ((const float4*)bias)[lane];
    acc.x = fmaxf(acc.x + bb.x, 0.f);
    acc.y = fmaxf(acc.y + bb.y, 0.f);
    acc.z = fmaxf(acc.z + bb.z, 0.f);
    acc.w = fmaxf(acc.w + bb.w, 0.f);

    if (POOL) {
        int g = g_batch[d];
        float* p = g_pool + g * HID + lane * 4;
        atomicAdd(p + 0, acc.x);
        atomicAdd(p + 1, acc.y);
        atomicAdd(p + 2, acc.z);
        atomicAdd(p + 3, acc.w);
    } else {
        ((float4*)(out + (size_t)d * HID))[lane] = acc;
    }
}

// ---------------- classifier head ----------------
__global__ void head_kernel(const float* __restrict__ Wc,
                            const float* __restrict__ bc,
                            float* __restrict__ out) {
    int g = blockIdx.x;
    int lane = threadIdx.x;
    float s = 0.f;
#pragma unroll
    for (int j = lane; j < HID; j += 32) s += g_pool[g * HID + j] * Wc[j];
#pragma unroll
    for (int o = 16; o; o >>= 1) s += __shfl_xor_sync(0xffffffffu, s, o);
    if (lane == 0) {
        float c = fmaxf((float)g_gcnt[g], 1.f);
        float v = s / c + bc[0];
        out[g] = 1.f / (1.f + expf(-v));
    }
}

// ---------------- launch ----------------
extern "C" void kernel_launch(void* const* d_in, const int* in_sizes, int n_in,
                              void* d_out, int out_size) {
    const float* x    = (const float*)d_in[0];
    const void*  edge = d_in[1];
    const void*  batch= d_in[2];
    const float* W1   = (const float*)d_in[3];
    const float* as1  = (const float*)d_in[4];
    const float* ad1  = (const float*)d_in[5];
    const float* b1   = (const float*)d_in[6];
    const float* W2   = (const float*)d_in[7];
    const float* as2  = (const float*)d_in[8];
    const float* ad2  = (const float*)d_in[9];
    const float* b2   = (const float*)d_in[10];
    const float* Wc   = (const float*)d_in[11];
    const float* bc   = (const float*)d_in[12];
    float* out = (float*)d_out;
    (void)in_sizes; (void)n_in; (void)out_size;

    float* bufA; cudaGetSymbolAddress((void**)&bufA, g_bufA);
    __nv_bfloat16* hb; cudaGetSymbolAddress((void**)&hb, g_hb);

    const int EB = (ET + 255) / 256;
    const int HB = (NE + 255) / 256;
    const int WB = (NN + 7) / 8;
    const int GB = (NN + 127) / 128;

    const int SMEM1 = 128 * (IND + 8) * 2 + IND * (HID + 8) * 2;  // 137216
    const int SMEM2 = 128 * (HID + 8) * 2 + HID * (HID + 8) * 2;  // 69632
    cudaFuncSetAttribute(mma_gemm_kernel<IND>,
                         cudaFuncAttributeMaxDynamicSharedMemorySize, SMEM1);
    cudaFuncSetAttribute(mma_gemm_kernel<HID>,
                         cudaFuncAttributeMaxDynamicSharedMemorySize, SMEM2);

    detect_kernel<<<1, 256>>>((const unsigned*)edge, (const unsigned*)batch);
    zero_kernel<<<64, 256>>>();
    hist_kernel<<<HB, 256>>>(edge, batch);
    scanA_kernel<<<SCAN_B, 256>>>();
    scanB_kernel<<<1, 256>>>();
    scanC_kernel<<<SCAN_B, 256>>>();
    fill_kernel<<<EB, 256>>>(edge);

    // ---- layer 1 ----
    mma_gemm_kernel<IND><<<GB, 256, SMEM1>>>(x, W1, hb, NN);
    alpha_kernel<<<WB, 256>>>(hb, as1, ad1);
    attn_kernel<0><<<WB, 256>>>(hb, b1, bufA);

    // ---- layer 2 ----
    mma_gemm_kernel<HID><<<GB, 256, SMEM2>>>(bufA, W2, hb, NN);
    alpha_kernel<<<WB, 256>>>(hb, as2, ad2);
    attn_kernel<1><<<WB, 256>>>(hb, b2, nullptr);

    head_kernel<<<NG, 32>>>(Wc, bc, out);
}

// round 11
// speedup vs baseline: 1.6864x; 1.1268x over previous
#include <cuda_runtime.h>
#include <cuda_bf16.h>
#include <cstdint>
#include <math.h>

#define NN   50000
#define NE   800000
#define ET   850000   // NE + NN self loops
#define IND  256
#define HID  128
#define NG   64
#define NEG_SLOPE 0.2f
#define SCAN_B ((NN + 255) / 256)   // 196

// ---------------- scratch (no allocations allowed) ----------------
__device__ float          g_bufA[NN * HID];   // fp32 attn output / gemm2 input
__device__ __nv_bfloat16  g_hb[NN * HID];     // bf16 h for gathering (12.8 MB)
__device__ float g_as[NN];
__device__ float g_ad[NN];
__device__ float g_w[ET];
__device__ int   g_batch[NN];
__device__ int   g_counts[NN];
__device__ int   g_roff[NN + 1];
__device__ int   g_cursor[NN];
__device__ int   g_csr[ET];
__device__ int   g_bsum[SCAN_B];
__device__ float g_pool[NG * HID];
__device__ int   g_gcnt[NG];
__device__ int   g_flag[2];

// ---------------- fused detect (block 0) + zero scratch (all blocks) ----------------
__global__ void dz_kernel(const unsigned* __restrict__ e,
                          const unsigned* __restrict__ b) {
    int stride = gridDim.x * blockDim.x;
    int i0 = blockIdx.x * blockDim.x + threadIdx.x;
    for (int j = i0; j < NN; j += stride) g_counts[j] = 1;   // 1 = self loop
    for (int j = i0; j < NG * HID; j += stride) g_pool[j] = 0.f;
    for (int j = i0; j < NG; j += stride) g_gcnt[j] = 0;
    if (blockIdx.x == 0) {
        __shared__ int r[2];
        int t = threadIdx.x;
        if (t < 2) r[t] = 0;
        __syncthreads();
        int a = 0;
        for (int i = t; i < 1024; i += 256) a |= (e[2 * i + 1] != 0u);
        int bb = (b[NN - 1 - 2 * t] != 0u);
        if (a) atomicOr(&r[0], 1);
        if (bb) atomicOr(&r[1], 1);
        __syncthreads();
        if (t == 0) { g_flag[0] = !r[0]; g_flag[1] = !r[1]; }
    }
}

// ---------------- histogram over dst + batch decode ----------------
__global__ void hist_kernel(const void* __restrict__ edge,
                            const void* __restrict__ batch) {
    int e64 = g_flag[0], b64 = g_flag[1];
    int i = blockIdx.x * blockDim.x + threadIdx.x;
    if (i < NE) {
        int d = e64 ? (int)((const long long*)edge)[NE + i]
                    : ((const int*)edge)[NE + i];
        atomicAdd(&g_counts[d], 1);
    }
    if (i < NN) {
        int b = b64 ? (int)((const long long*)batch)[i]
                    : ((const int*)batch)[i];
        g_batch[i] = b;
        atomicAdd(&g_gcnt[b], 1);
    }
}

// ---------------- scan step A: per-block exclusive scan + block sums ----------------
__global__ void scanA_kernel() {
    __shared__ int ws[8];
    int i = blockIdx.x * 256 + threadIdx.x;
    int lane = threadIdx.x & 31, wrp = threadIdx.x >> 5;
    int v = (i < NN) ? g_counts[i] : 0;
    int incl = v;
#pragma unroll
    for (int o = 1; o < 32; o <<= 1) {
        int t = __shfl_up_sync(0xffffffffu, incl, o);
        if (lane >= o) incl += t;
    }
    if (lane == 31) ws[wrp] = incl;
    __syncthreads();
    if (threadIdx.x < 8) {
        int s = ws[threadIdx.x];
        int inc2 = s;
#pragma unroll
        for (int o = 1; o < 8; o <<= 1) {
            int t = __shfl_up_sync(0xffu, inc2, o);
            if (threadIdx.x >= (unsigned)o) inc2 += t;
        }
        ws[threadIdx.x] = inc2 - s;
        if (threadIdx.x == 7) g_bsum[blockIdx.x] = inc2;
    }
    __syncthreads();
    if (i < NN) g_roff[i] = ws[wrp] + incl - v;
}

// ---------------- scan step C: each block locally reduces its bsum prefix ----------------
__global__ void scanC_kernel() {
    __shared__ int ssum[8];
    int t = threadIdx.x, bid = blockIdx.x;
    int lane = t & 31, wrp = t >> 5;
    int v = (t < SCAN_B && t < bid) ? g_bsum[t] : 0;
#pragma unroll
    for (int o = 16; o; o >>= 1) v += __shfl_xor_sync(0xffffffffu, v, o);
    if (lane == 0) ssum[wrp] = v;
    __syncthreads();
    if (t == 0) {
        int s = 0;
#pragma unroll
        for (int j = 0; j < 8; j++) s += ssum[j];
        ssum[0] = s;
    }
    __syncthreads();
    int off = ssum[0];
    int i = bid * 256 + t;
    if (i == 0) g_roff[NN] = ET;
    if (i < NN) {
        int r = g_roff[i] + off;
        g_roff[i] = r;
        g_cursor[i] = r;
    }
}

// ---------------- CSR fill (decodes edge input directly) ----------------
__global__ void fill_kernel(const void* __restrict__ edge) {
    int e64 = g_flag[0];
    int i = blockIdx.x * blockDim.x + threadIdx.x;
    if (i >= ET) return;
    int s, d;
    if (i < NE) {
        if (e64) {
            s = (int)((const long long*)edge)[i];
            d = (int)((const long long*)edge)[NE + i];
        } else {
            s = ((const int*)edge)[i];
            d = ((const int*)edge)[NE + i];
        }
    } else {
        s = d = i - NE;
    }
    int p = atomicAdd(&g_cursor[d], 1);
    g_csr[p] = s;
}

// ================= bf16 mma.sync GEMM + fused alpha epilogue =================
// C[M,128](bf16) = A[M,K](fp32->bf16) @ W[K,128](fp32->bf16), fp32 accum.
// K staged in 128-wide chunks (69.6KB smem -> 2 CTA/SM).
// Block: 128x128 tile, 256 threads = 4(M) x 2(N) warps, warp = 32x64.

__device__ __forceinline__ uint32_t smem_u32(const void* p) {
    uint32_t a;
    asm("{ .reg .u64 t; cvta.to.shared.u64 t, %1; cvt.u32.u64 %0, t; }"
        : "=r"(a) : "l"(p));
    return a;
}

#define LDM_X4(r0, r1, r2, r3, addr) \
    asm volatile("ldmatrix.sync.aligned.m8n8.x4.shared.b16 {%0,%1,%2,%3}, [%4];" \
        : "=r"(r0), "=r"(r1), "=r"(r2), "=r"(r3) : "r"(addr))
#define LDM_X4T(r0, r1, r2, r3, addr) \
    asm volatile("ldmatrix.sync.aligned.m8n8.x4.trans.shared.b16 {%0,%1,%2,%3}, [%4];" \
        : "=r"(r0), "=r"(r1), "=r"(r2), "=r"(r3) : "r"(addr))
#define MMA16816(c, a0, a1, a2, a3, b0, b1) \
    asm volatile("mma.sync.aligned.m16n8k16.row.col.f32.bf16.bf16.f32 " \
        "{%0,%1,%2,%3}, {%4,%5,%6,%7}, {%8,%9}, {%0,%1,%2,%3};" \
        : "+f"((c)[0]), "+f"((c)[1]), "+f"((c)[2]), "+f"((c)[3]) \
        : "r"(a0), "r"(a1), "r"(a2), "r"(a3), "r"(b0), "r"(b1))

template <int K>
__global__ void __launch_bounds__(256, 2)
mma_gemm_kernel(const float* __restrict__ A, const float* __restrict__ W,
                __nv_bfloat16* __restrict__ C, int M,
                const float* __restrict__ asrc, const float* __restrict__ adst) {
    constexpr int KC = 128;           // K chunk
    constexpr int LD = 136;           // 128+8 bf16 -> conflict-free ldmatrix
    extern __shared__ char smem[];
    __nv_bfloat16* sA = (__nv_bfloat16*)smem;                    // 128 x LD
    __nv_bfloat16* sW = (__nv_bfloat16*)(smem + 128 * LD * 2);   // KC x LD

    int tid = threadIdx.x;
    int wid = tid >> 5, lane = tid & 31;
    int m0 = blockIdx.x * 128;

    const int wm = (wid & 3) * 32;    // warp M offset
    const int wn = (wid >> 2) * 64;   // warp N offset
    int gq = lane >> 2, tg = lane & 3;

    float acc[2][8][4];
#pragma unroll
    for (int mt = 0; mt < 2; mt++)
#pragma unroll
        for (int nt = 0; nt < 8; nt++)
#pragma unroll
            for (int j = 0; j < 4; j++) acc[mt][nt][j] = 0.f;

    uint32_t sAu = smem_u32(sA);
    uint32_t sWu = smem_u32(sW);

    for (int kc = 0; kc < K; kc += KC) {
        // ---- stage A chunk (fp32 -> bf16)
        for (int idx = tid; idx < 128 * KC / 8; idx += 256) {
            int row = idx >> 4;
            int kv  = (idx & 15) * 8;
            int gm  = m0 + row;
            float4 f0 = make_float4(0.f, 0.f, 0.f, 0.f), f1 = f0;
            if (gm < M) {
                f0 = *(const float4*)(A + (size_t)gm * K + kc + kv);
                f1 = *(const float4*)(A + (size_t)gm * K + kc + kv + 4);
            }
            __nv_bfloat162 p0 = __floats2bfloat162_rn(f0.x, f0.y);
            __nv_bfloat162 p1 = __floats2bfloat162_rn(f0.z, f0.w);
            __nv_bfloat162 p2 = __floats2bfloat162_rn(f1.x, f1.y);
            __nv_bfloat162 p3 = __floats2bfloat162_rn(f1.z, f1.w);
            uint4 pk;
            pk.x = *(unsigned*)&p0; pk.y = *(unsigned*)&p1;
            pk.z = *(unsigned*)&p2; pk.w = *(unsigned*)&p3;
            *(uint4*)(sA + row * LD + kv) = pk;
        }
        // ---- stage W chunk; W is [K][128] row-major
        for (int idx = tid; idx < KC * HID / 8; idx += 256) {
            int k = idx >> 4;
            int n = (idx & 15) * 8;
            float4 f0 = *(const float4*)(W + (size_t)(kc + k) * HID + n);
            float4 f1 = *(const float4*)(W + (size_t)(kc + k) * HID + n + 4);
            __nv_bfloat162 p0 = __floats2bfloat162_rn(f0.x, f0.y);
            __nv_bfloat162 p1 = __floats2bfloat162_rn(f0.z, f0.w);
            __nv_bfloat162 p2 = __floats2bfloat162_rn(f1.x, f1.y);
            __nv_bfloat162 p3 = __floats2bfloat162_rn(f1.z, f1.w);
            uint4 pk;
            pk.x = *(unsigned*)&p0; pk.y = *(unsigned*)&p1;
            pk.z = *(unsigned*)&p2; pk.w = *(unsigned*)&p3;
            *(uint4*)(sW + k * LD + n) = pk;
        }
        __syncthreads();

#pragma unroll
        for (int ks = 0; ks < KC / 16; ks++) {
            int k = ks * 16;
            uint32_t a[2][4];
#pragma unroll
            for (int mt = 0; mt < 2; mt++) {
                uint32_t addr = sAu +
                    ((wm + mt * 16 + (lane & 15)) * LD + k + (lane >> 4) * 8) * 2;
                LDM_X4(a[mt][0], a[mt][1], a[mt][2], a[mt][3], addr);
            }
            uint32_t b[8][2];
#pragma unroll
            for (int np = 0; np < 4; np++) {
                uint32_t addr = sWu +
                    ((k + (lane & 15)) * LD + wn + np * 16 + (lane >> 4) * 8) * 2;
                uint32_t r0, r1, r2, r3;
                LDM_X4T(r0, r1, r2, r3, addr);
                b[np * 2][0] = r0;     b[np * 2][1] = r1;
                b[np * 2 + 1][0] = r2; b[np * 2 + 1][1] = r3;
            }
#pragma unroll
            for (int mt = 0; mt < 2; mt++)
#pragma unroll
                for (int nt = 0; nt < 8; nt++)
                    MMA16816(acc[mt][nt], a[mt][0], a[mt][1], a[mt][2], a[mt][3],
                             b[nt][0], b[nt][1]);
        }
        __syncthreads();
    }

    // ---- epilogue 1: bf16 stores of h
#pragma unroll
    for (int mt = 0; mt < 2; mt++) {
        int r0 = m0 + wm + mt * 16 + gq;
        int r1 = r0 + 8;
#pragma unroll
        for (int nt = 0; nt < 8; nt++) {
            int c = wn + nt * 8 + tg * 2;
            if (r0 < M) {
                __nv_bfloat162 p = __floats2bfloat162_rn(acc[mt][nt][0], acc[mt][nt][1]);
                *(unsigned*)(C + (size_t)r0 * HID + c) = *(unsigned*)&p;
            }
            if (r1 < M) {
                __nv_bfloat162 p = __floats2bfloat162_rn(acc[mt][nt][2], acc[mt][nt][3]);
                *(unsigned*)(C + (size_t)r1 * HID + c) = *(unsigned*)&p;
            }
        }
    }

    // ---- epilogue 2: fused alpha dots (fp32 accumulators)
    float* sal = (float*)smem;   // [128 rows][2 nhalf][2 (s,d)] = 2KB (staging done)
    int nh = wid >> 2;
#pragma unroll
    for (int mt = 0; mt < 2; mt++) {
        float s0 = 0.f, d0 = 0.f, s1 = 0.f, d1 = 0.f;
#pragma unroll
        for (int nt = 0; nt < 8; nt++) {
            int c = wn + nt * 8 + tg * 2;
            float a0 = __ldg(&asrc[c]), a1 = __ldg(&asrc[c + 1]);
            float e0 = __ldg(&adst[c]), e1 = __ldg(&adst[c + 1]);
            s0 += acc[mt][nt][0] * a0 + acc[mt][nt][1] * a1;
            d0 += acc[mt][nt][0] * e0 + acc[mt][nt][1] * e1;
            s1 += acc[mt][nt][2] * a0 + acc[mt][nt][3] * a1;
            d1 += acc[mt][nt][2] * e0 + acc[mt][nt][3] * e1;
        }
#pragma unroll
        for (int o = 1; o <= 2; o <<= 1) {
            s0 += __shfl_xor_sync(0xffffffffu, s0, o);
            d0 += __shfl_xor_sync(0xffffffffu, d0, o);
            s1 += __shfl_xor_sync(0xffffffffu, s1, o);
            d1 += __shfl_xor_sync(0xffffffffu, d1, o);
        }
        if (tg == 0) {
            int row0 = wm + mt * 16 + gq, row1 = row0 + 8;
            sal[(row0 * 2 + nh) * 2 + 0] = s0;
            sal[(row0 * 2 + nh) * 2 + 1] = d0;
            sal[(row1 * 2 + nh) * 2 + 0] = s1;
            sal[(row1 * 2 + nh) * 2 + 1] = d1;
        }
    }
    __syncthreads();
    if (tid < 128) {
        int m = m0 + tid;
        if (m < M) {
            g_as[m] = sal[(tid * 2 + 0) * 2 + 0] + sal[(tid * 2 + 1) * 2 + 0];
            g_ad[m] = sal[(tid * 2 + 0) * 2 + 1] + sal[(tid * 2 + 1) * 2 + 1];
        }
    }
}

// ---------------- fused attention: warp per dst, bf16 gathers ----------------
template <int POOL>
__global__ void __launch_bounds__(256)
attn_kernel(const __nv_bfloat16* __restrict__ h, const float* __restrict__ bias,
            float* __restrict__ out) {
    int d = blockIdx.x * 8 + (threadIdx.x >> 5);
    if (d >= NN) return;
    int lane = threadIdx.x & 31;
    int beg = g_roff[d], end = g_roff[d + 1];
    float add = g_ad[d];

    float den = 0.f;
    for (int i = beg + lane; i < end; i += 32) {
        float e = __ldg(&g_as[g_csr[i]]) + add;
        e = e > 0.f ? e : NEG_SLOPE * e;
        float w = __expf(e);
        g_w[i] = w;
        den += w;
    }
#pragma unroll
    for (int o = 16; o; o >>= 1) den += __shfl_xor_sync(0xffffffffu, den, o);
    float inv = 1.f / den;
    __syncwarp();

    float4 acc = make_float4(0.f, 0.f, 0.f, 0.f);
    int i = beg;
    for (; i + 4 <= end; i += 4) {
        int   s0 = g_csr[i],     s1 = g_csr[i + 1];
        int   s2 = g_csr[i + 2], s3 = g_csr[i + 3];
        float c0 = g_w[i] * inv,     c1 = g_w[i + 1] * inv;
        float c2 = g_w[i + 2] * inv, c3 = g_w[i + 3] * inv;
        uint2 v0 = __ldg(&((const uint2*)(h + (size_t)s0 * HID))[lane]);
        uint2 v1 = __ldg(&((const uint2*)(h + (size_t)s1 * HID))[lane]);
        uint2 v2 = __ldg(&((const uint2*)(h + (size_t)s2 * HID))[lane]);
        uint2 v3 = __ldg(&((const uint2*)(h + (size_t)s3 * HID))[lane]);
        float2 a0 = __bfloat1622float2(*(__nv_bfloat162*)&v0.x);
        float2 b0 = __bfloat1622float2(*(__nv_bfloat162*)&v0.y);
        float2 a1 = __bfloat1622float2(*(__nv_bfloat162*)&v1.x);
        float2 b1 = __bfloat1622float2(*(__nv_bfloat162*)&v1.y);
        float2 a2 = __bfloat1622float2(*(__nv_bfloat162*)&v2.x);
        float2 b2 = __bfloat1622float2(*(__nv_bfloat162*)&v2.y);
        float2 a3 = __bfloat1622float2(*(__nv_bfloat162*)&v3.x);
        float2 b3 = __bfloat1622float2(*(__nv_bfloat162*)&v3.y);
        acc.x += c0 * a0.x + c1 * a1.x + c2 * a2.x + c3 * a3.x;
        acc.y += c0 * a0.y + c1 * a1.y + c2 * a2.y + c3 * a3.y;
        acc.z += c0 * b0.x + c1 * b1.x + c2 * b2.x + c3 * b3.x;
        acc.w += c0 * b0.y + c1 * b1.y + c2 * b2.y + c3 * b3.y;
    }
    for (; i < end; i++) {
        int s = g_csr[i];
        float c = g_w[i] * inv;
        uint2 v = __ldg(&((const uint2*)(h + (size_t)s * HID))[lane]);
        float2 a = __bfloat1622float2(*(__nv_bfloat162*)&v.x);
        float2 b = __bfloat1622float2(*(__nv_bfloat162*)&v.y);
        acc.x += c * a.x; acc.y += c * a.y;
        acc.z += c * b.x; acc.w += c * b.y;
    }

    float4 bb = ((const float4*)bias)[lane];
    acc.x = fmaxf(acc.x + bb.x, 0.f);
    acc.y = fmaxf(acc.y + bb.y, 0.f);
    acc.z = fmaxf(acc.z + bb.z, 0.f);
    acc.w = fmaxf(acc.w + bb.w, 0.f);

    if (POOL) {
        int g = g_batch[d];
        float* p = g_pool + g * HID + lane * 4;
        atomicAdd(p + 0, acc.x);
        atomicAdd(p + 1, acc.y);
        atomicAdd(p + 2, acc.z);
        atomicAdd(p + 3, acc.w);
    } else {
        ((float4*)(out + (size_t)d * HID))[lane] = acc;
    }
}

// ---------------- classifier head ----------------
__global__ void head_kernel(const float* __restrict__ Wc,
                            const float* __restrict__ bc,
                            float* __restrict__ out) {
    int g = blockIdx.x;
    int lane = threadIdx.x;
    float s = 0.f;
#pragma unroll
    for (int j = lane; j < HID; j += 32) s += g_pool[g * HID + j] * Wc[j];
#pragma unroll
    for (int o = 16; o; o >>= 1) s += __shfl_xor_sync(0xffffffffu, s, o);
    if (lane == 0) {
        float c = fmaxf((float)g_gcnt[g], 1.f);
        float v = s / c + bc[0];
        out[g] = 1.f / (1.f + expf(-v));
    }
}

// ---------------- launch ----------------
extern "C" void kernel_launch(void* const* d_in, const int* in_sizes, int n_in,
                              void* d_out, int out_size) {
    const float* x    = (const float*)d_in[0];
    const void*  edge = d_in[1];
    const void*  batch= d_in[2];
    const float* W1   = (const float*)d_in[3];
    const float* as1  = (const float*)d_in[4];
    const float* ad1  = (const float*)d_in[5];
    const float* b1   = (const float*)d_in[6];
    const float* W2   = (const float*)d_in[7];
    const float* as2  = (const float*)d_in[8];
    const float* ad2  = (const float*)d_in[9];
    const float* b2   = (const float*)d_in[10];
    const float* Wc   = (const float*)d_in[11];
    const float* bc   = (const float*)d_in[12];
    float* out = (float*)d_out;
    (void)in_sizes; (void)n_in; (void)out_size;

    float* bufA; cudaGetSymbolAddress((void**)&bufA, g_bufA);
    __nv_bfloat16* hb; cudaGetSymbolAddress((void**)&hb, g_hb);

    const int EB = (ET + 255) / 256;
    const int HB = (NE + 255) / 256;
    const int WB = (NN + 7) / 8;
    const int GB = (NN + 127) / 128;

    const int SMEM = 2 * 128 * 136 * 2;   // 69632 for both gemms
    cudaFuncSetAttribute(mma_gemm_kernel<IND>,
                         cudaFuncAttributeMaxDynamicSharedMemorySize, SMEM);
    cudaFuncSetAttribute(mma_gemm_kernel<HID>,
                         cudaFuncAttributeMaxDynamicSharedMemorySize, SMEM);

    dz_kernel<<<64, 256>>>((const unsigned*)edge, (const unsigned*)batch);  // 1
    hist_kernel<<<HB, 256>>>(edge, batch);                                  // 2
    scanA_kernel<<<SCAN_B, 256>>>();                                        // 3
    mma_gemm_kernel<IND><<<GB, 256, SMEM>>>(x, W1, hb, NN, as1, ad1);       // 4 (profiled)
    scanC_kernel<<<SCAN_B, 256>>>();                                        // 5
    fill_kernel<<<EB, 256>>>(edge);                                         // 6
    attn_kernel<0><<<WB, 256>>>(hb, b1, bufA);                              // 7
    mma_gemm_kernel<HID><<<GB, 256, SMEM>>>(bufA, W2, hb, NN, as2, ad2);    // 8
    attn_kernel<1><<<WB, 256>>>(hb, b2, nullptr);                           // 9
    head_kernel<<<NG, 32>>>(Wc, bc, out);                                   // 10
}